// round 4
// baseline (speedup 1.0000x reference)
#include <cuda_runtime.h>
#include <cstdint>
#include <cstddef>

#define BB  8
#define CC  256
#define NQ  4096
#define NK  4096
#define KNN 8

// Scratch (device globals; no runtime allocation allowed)
__device__ int   g_idx[(size_t)BB * NQ * KNN];            // 1 MiB
__device__ float g_kft[(size_t)BB * NK * CC];             // 32 MiB, (B, NK, C)

// ---------------------------------------------------------------------------
// 1) Brute-force KNN. Arithmetic deliberately mirrors the XLA lowering:
//    - dot  : cuBLAS fp32 GEMM accumulation chain (FMA, ascending K)
//    - qq,kk: XLA loop-fusion reduce -> UNFUSED mul/add, left-to-right
//    - d    : ((qq - 2*dot) + kk), left-associative, unfused
//    All via __f*_rn intrinsics so nvcc/ptxas cannot re-contract.
//    Top-8 sorted ascending in registers; strict '<' insertion preserves
//    lax.top_k tie stability (lower index first).
// ---------------------------------------------------------------------------
__global__ void knn_kernel(const float* __restrict__ qc,
                           const float* __restrict__ kc) {
    extern __shared__ float4 s_key[];                     // NK * 16B = 64 KiB
    const int b  = blockIdx.x >> 4;                       // 16 tiles per batch
    const int qt = blockIdx.x & 15;
    const int q  = qt * 256 + threadIdx.x;

    const float* kcb = kc + (size_t)b * 3 * NK;
    for (int i = threadIdx.x; i < NK; i += 256) {
        float kx = kcb[i], ky = kcb[NK + i], kz = kcb[2 * NK + i];
        // kk = (kx*kx + ky*ky) + kz*kz, every op rounded separately (XLA fusion)
        float kk = __fadd_rn(__fadd_rn(__fmul_rn(kx, kx), __fmul_rn(ky, ky)),
                             __fmul_rn(kz, kz));
        s_key[i] = make_float4(kx, ky, kz, kk);
    }
    __syncthreads();

    const float* qcb = qc + (size_t)b * 3 * NQ;
    const float qx = qcb[q], qy = qcb[NQ + q], qz = qcb[2 * NQ + q];
    const float qq = __fadd_rn(__fadd_rn(__fmul_rn(qx, qx), __fmul_rn(qy, qy)),
                               __fmul_rn(qz, qz));

    float bd[KNN];
    int   bi[KNN];
#pragma unroll
    for (int k = 0; k < KNN; k++) { bd[k] = 3.402823466e38f; bi[k] = 0; }

#pragma unroll 4
    for (int j = 0; j < NK; j++) {
        float4 s  = s_key[j];
        // cuBLAS K-chain: acc = rn(qx*kx); acc = fma(qy,ky,acc); acc = fma(qz,kz,acc)
        float dot = __fmul_rn(qx, s.x);
        dot = __fmaf_rn(qy, s.y, dot);
        dot = __fmaf_rn(qz, s.z, dot);
        // d = (qq - 2*dot) + kk, unfused, left-associative
        float d = __fadd_rn(__fsub_rn(qq, __fmul_rn(2.0f, dot)), s.w);
        if (d < bd[KNN - 1]) {
            bd[KNN - 1] = d; bi[KNN - 1] = j;
#pragma unroll
            for (int k = KNN - 1; k > 0; k--) {
                if (bd[k] < bd[k - 1]) {                  // strict: stable for ties
                    float td = bd[k]; bd[k] = bd[k - 1]; bd[k - 1] = td;
                    int   ti = bi[k]; bi[k] = bi[k - 1]; bi[k - 1] = ti;
                }
            }
        }
    }

    int* op = g_idx + ((size_t)b * NQ + q) * KNN;
#pragma unroll
    for (int k = 0; k < KNN; k++) op[k] = bi[k];
}

// ---------------------------------------------------------------------------
// 2) Transpose key_features (B, C, NK) -> (B, NK, C) so neighbor rows are
//    contiguous 1 KiB segments for the gather.
// ---------------------------------------------------------------------------
__global__ void transpose_kernel(const float* __restrict__ kf) {
    __shared__ float tile[32][33];
    const int b  = blockIdx.z;
    const int n0 = blockIdx.x * 32;
    const int c0 = blockIdx.y * 32;
    const float* src = kf + (size_t)b * CC * NK;
#pragma unroll
    for (int i = 0; i < 4; i++) {
        int c = c0 + threadIdx.y + i * 8;
        tile[threadIdx.y + i * 8][threadIdx.x] = src[(size_t)c * NK + n0 + threadIdx.x];
    }
    __syncthreads();
    float* dst = g_kft + (size_t)b * NK * CC;
#pragma unroll
    for (int i = 0; i < 4; i++) {
        int n = n0 + threadIdx.y + i * 8;
        dst[(size_t)n * CC + c0 + threadIdx.x] = tile[threadIdx.x][threadIdx.y + i * 8];
    }
}

// ---------------------------------------------------------------------------
// 3) Lower half of the output: out[b, c, q, k] = kf[b, c, idx] - qf[b, c, q].
//    Block = 32 queries (256 (q,k) slots), looping over 32-channel chunks.
//    Load phase: each slot's 128B row chunk read by 8 lanes as one float4 each
//    (sector-perfect). Write phase: 256 threads emit 1 KiB contiguous stores
//    per channel; SMEM padded to 33 for conflict-free strided reads.
// ---------------------------------------------------------------------------
__global__ void gather_kernel(const float* __restrict__ qf,
                              float* __restrict__ out) {
    __shared__ float s_nb[256][33];
    __shared__ float qsm[32][33];
    __shared__ int   s_idx[256];

    const int b  = blockIdx.x >> 7;                       // 128 tiles per batch
    const int qt = blockIdx.x & 127;
    const int q0 = qt * 32;
    const int t  = threadIdx.x;

    s_idx[t] = g_idx[((size_t)b * NQ + q0) * KNN + t];
    __syncthreads();

    const float* kftb = g_kft + (size_t)b * NK * CC;
    const float* qfb  = qf + (size_t)b * CC * NQ;
    const int qloc = t >> 3;

    for (int c0 = 0; c0 < CC; c0 += 32) {
#pragma unroll
        for (int r = 0; r < 8; r++) {
            int s = r * 32 + (t >> 3);
            int n = s_idx[s];
            const float4* row = (const float4*)(kftb + (size_t)n * CC + c0);
            float4 v = row[t & 7];
            int cc = (t & 7) * 4;
            s_nb[s][cc + 0] = v.x; s_nb[s][cc + 1] = v.y;
            s_nb[s][cc + 2] = v.z; s_nb[s][cc + 3] = v.w;
        }
#pragma unroll
        for (int rr = 0; rr < 4; rr++) {
            int i = rr * 8 + (t >> 5);
            qsm[i][t & 31] = qfb[(size_t)(c0 + i) * NQ + q0 + (t & 31)];
        }
        __syncthreads();

        float* outb = out + ((size_t)b * 2 * CC + c0) * NQ * KNN + (size_t)q0 * KNN;
#pragma unroll
        for (int i = 0; i < 32; i++) {
            outb[(size_t)i * (NQ * KNN) + t] = s_nb[t][i] - qsm[i][qloc];
        }
        __syncthreads();
    }
}

// ---------------------------------------------------------------------------
// 4) Upper half: out[b, C+c, q, k] = qf[b, c, q] broadcast over k.
//    qf is linear in tid; each thread writes 32B (2x float4), fully coalesced.
// ---------------------------------------------------------------------------
__global__ void upper_kernel(const float* __restrict__ qf,
                             float* __restrict__ out) {
    const size_t tid = (size_t)blockIdx.x * 256 + threadIdx.x;   // B*C*NQ threads
    const float v = qf[tid];
    const size_t b   = tid >> 20;                                 // C*NQ = 2^20
    const size_t rem = tid & ((1u << 20) - 1);
    const size_t off = ((b * 2097152) + 1048576 + rem) * KNN;     // 512*4096 = 2097152
    float4 v4 = make_float4(v, v, v, v);
    float4* o = (float4*)(out + off);
    o[0] = v4;
    o[1] = v4;
}

// ---------------------------------------------------------------------------
extern "C" void kernel_launch(void* const* d_in, const int* in_sizes, int n_in,
                              void* d_out, int out_size) {
    const float* query_coords   = (const float*)d_in[0];
    const float* query_features = (const float*)d_in[1];
    const float* key_coords     = (const float*)d_in[2];
    const float* key_features   = (const float*)d_in[3];
    float* out = (float*)d_out;
    (void)in_sizes; (void)n_in; (void)out_size;

    cudaFuncSetAttribute(knn_kernel,
                         cudaFuncAttributeMaxDynamicSharedMemorySize, NK * 16);

    knn_kernel<<<BB * (NQ / 256), 256, NK * 16>>>(query_coords, key_coords);
    transpose_kernel<<<dim3(NK / 32, CC / 32, BB), dim3(32, 8)>>>(key_features);
    upper_kernel<<<(BB * CC * NQ) / 256, 256>>>(query_features, out);
    gather_kernel<<<BB * (NQ / 32), 256>>>(query_features, out);
}